// round 2
// baseline (speedup 1.0000x reference)
#include <cuda_runtime.h>
#include <math_constants.h>

// Fixed shapes
#define B     32
#define H     8192
#define HO    4096
#define W4    64        // 256 floats / 4
#define NBLK  256       // persistent grid: <=2 CTAs/SM -> all resident wave 1
#define RPB   16        // output rows per block per batch (4096/256)
#define SLOTS 4         // scratch ring depth (4 * 4 MiB = 16 MiB, L2-resident)

// L2-resident scratch ring for pooled (un-normalized) values.
__device__ float4  g_scratch[SLOTS * HO * W4];   // 16 MiB
__device__ int      g_pool_cnt[B];
__device__ int      g_norm_cnt[B];
__device__ unsigned g_min[B];
__device__ unsigned g_max[B];

__device__ __forceinline__ unsigned enc_f(float f) {
    unsigned u = __float_as_uint(f);
    return (u & 0x80000000u) ? ~u : (u | 0x80000000u);
}
__device__ __forceinline__ float dec_f(unsigned e) {
    unsigned u = (e & 0x80000000u) ? (e ^ 0x80000000u) : ~e;
    return __uint_as_float(u);
}

__global__ void init_kernel() {
    int i = threadIdx.x;
    if (i < B) {
        g_pool_cnt[i] = 0;
        g_norm_cnt[i] = 0;
        g_min[i] = 0xFFFFFFFFu;
        g_max[i] = 0x00000000u;
    }
}

__global__ __launch_bounds__(256, 2)
void fused_kernel(const float4* __restrict__ x, float4* __restrict__ out) {
    const int tid = threadIdx.x;
    const int w4  = tid & 63;
    const int sub = tid >> 6;             // 0..3
    const int blk = blockIdx.x;
    const int r0  = blk * RPB + sub * 4;  // this thread's first output row
    const int lane = tid & 31;
    const int wid  = tid >> 5;

    __shared__ float s_mn[8], s_mx[8];

    for (int step = 0; step <= B; step++) {
        // ---------------- Phase A: pool batch 'step' into scratch ring ----
        if (step < B) {
            const int b = step;
            if (b >= SLOTS) {
                // slot reuse guard: norm of batch b-SLOTS must be fully read
                if (tid == 0) {
                    while (*(volatile int*)&g_norm_cnt[b - SLOTS] < NBLK) __nanosleep(32);
                }
                __syncthreads();
            }
            const float4* __restrict__ xb = x + (size_t)b * H * W4;
            float4* __restrict__ sc = g_scratch + (size_t)(b % SLOTS) * HO * W4;

            float4 prev;
            if (r0 == 0) {
                prev = make_float4(-CUDART_INF_F, -CUDART_INF_F, -CUDART_INF_F, -CUDART_INF_F);
            } else {
                prev = __ldcs(&xb[(size_t)(2 * r0 - 1) * W4 + w4]);
            }
            float mn =  CUDART_INF_F;
            float mx = -CUDART_INF_F;
            #pragma unroll
            for (int i = 0; i < 4; i++) {
                const int r = r0 + i;
                float4 a = __ldcs(&xb[(size_t)(2 * r)     * W4 + w4]);
                float4 c = __ldcs(&xb[(size_t)(2 * r + 1) * W4 + w4]);
                float4 p;
                p.x = fmaxf(fmaxf(a.x, c.x), prev.x);
                p.y = fmaxf(fmaxf(a.y, c.y), prev.y);
                p.z = fmaxf(fmaxf(a.z, c.z), prev.z);
                p.w = fmaxf(fmaxf(a.w, c.w), prev.w);
                __stcg(&sc[(size_t)r * W4 + w4], p);
                mn = fminf(mn, fminf(fminf(p.x, p.y), fminf(p.z, p.w)));
                mx = fmaxf(mx, fmaxf(fmaxf(p.x, p.y), fmaxf(p.z, p.w)));
                prev = c;
            }
            // publish my scratch writes before the counter can be observed
            __threadfence();

            // block reduce min/max
            #pragma unroll
            for (int off = 16; off > 0; off >>= 1) {
                mn = fminf(mn, __shfl_xor_sync(0xFFFFFFFFu, mn, off));
                mx = fmaxf(mx, __shfl_xor_sync(0xFFFFFFFFu, mx, off));
            }
            if (lane == 0) { s_mn[wid] = mn; s_mx[wid] = mx; }
            __syncthreads();
            if (wid == 0) {
                mn = (lane < 8) ? s_mn[lane] :  CUDART_INF_F;
                mx = (lane < 8) ? s_mx[lane] : -CUDART_INF_F;
                #pragma unroll
                for (int off = 4; off > 0; off >>= 1) {
                    mn = fminf(mn, __shfl_xor_sync(0xFFFFFFFFu, mn, off));
                    mx = fmaxf(mx, __shfl_xor_sync(0xFFFFFFFFu, mx, off));
                }
                if (lane == 0) {
                    atomicMin(&g_min[b], enc_f(mn));
                    atomicMax(&g_max[b], enc_f(mx));
                    __threadfence();
                    atomicAdd(&g_pool_cnt[b], 1);
                }
            }
            __syncthreads();   // s_mn/s_mx reuse safety
        }

        // ---------------- Phase B: normalize batch 'step-1' ---------------
        if (step >= 1) {
            const int b = step - 1;
            if (tid == 0) {
                while (*(volatile int*)&g_pool_cnt[b] < NBLK) __nanosleep(32);
            }
            __syncthreads();

            const float mnv = dec_f(*(volatile unsigned*)&g_min[b]);
            const float mxv = dec_f(*(volatile unsigned*)&g_max[b]);
            const float inv = 1.0f / (mxv - mnv);

            const float4* __restrict__ sc = g_scratch + (size_t)(b % SLOTS) * HO * W4;
            float4* __restrict__ ob = out + (size_t)b * HO * W4;

            #pragma unroll
            for (int i = 0; i < 4; i++) {
                const int r = r0 + i;
                float4 v = __ldcg(&sc[(size_t)r * W4 + w4]);   // L2 hit, L1-bypass
                v.x = (v.x - mnv) * inv;
                v.y = (v.y - mnv) * inv;
                v.z = (v.z - mnv) * inv;
                v.w = (v.w - mnv) * inv;
                __stcs(&ob[(size_t)r * W4 + w4], v);           // streaming store
            }
            __syncthreads();   // all threads done reading the slot
            if (tid == 0) atomicAdd(&g_norm_cnt[b], 1);
        }
    }
}

extern "C" void kernel_launch(void* const* d_in, const int* in_sizes, int n_in,
                              void* d_out, int out_size) {
    (void)in_sizes; (void)n_in; (void)out_size;
    const float4* x = (const float4*)d_in[0];
    float4* out = (float4*)d_out;

    init_kernel<<<1, 32>>>();
    fused_kernel<<<NBLK, 256>>>(x, out);
}

// round 3
// speedup vs baseline: 1.9935x; 1.9935x over previous
#include <cuda_runtime.h>
#include <math_constants.h>

// Fixed shapes
#define B     32
#define H     8192
#define HO    4096
#define W4    64          // 256 floats / 4
#define GPB   128         // blocks (groups) per batch
#define ROWS  32          // output rows per block
#define RPT   8           // output rows per thread (ROWS / 4 subs)
#define NBLK  (B * GPB)   // 4096

// Per-batch sync/reduction state. Static-initialized for the first launch;
// the last finishing block of each batch resets it for the next graph replay.
__device__ unsigned g_min[B] = {
    0xFFFFFFFFu,0xFFFFFFFFu,0xFFFFFFFFu,0xFFFFFFFFu,0xFFFFFFFFu,0xFFFFFFFFu,0xFFFFFFFFu,0xFFFFFFFFu,
    0xFFFFFFFFu,0xFFFFFFFFu,0xFFFFFFFFu,0xFFFFFFFFu,0xFFFFFFFFu,0xFFFFFFFFu,0xFFFFFFFFu,0xFFFFFFFFu,
    0xFFFFFFFFu,0xFFFFFFFFu,0xFFFFFFFFu,0xFFFFFFFFu,0xFFFFFFFFu,0xFFFFFFFFu,0xFFFFFFFFu,0xFFFFFFFFu,
    0xFFFFFFFFu,0xFFFFFFFFu,0xFFFFFFFFu,0xFFFFFFFFu,0xFFFFFFFFu,0xFFFFFFFFu,0xFFFFFFFFu,0xFFFFFFFFu};
__device__ unsigned g_max[B];        // zero-init == encoded -inf side
__device__ int g_pool_cnt[B];        // zero-init
__device__ int g_done_cnt[B];        // zero-init

__device__ __forceinline__ unsigned enc_f(float f) {
    unsigned u = __float_as_uint(f);
    return (u & 0x80000000u) ? ~u : (u | 0x80000000u);
}
__device__ __forceinline__ float dec_f(unsigned e) {
    unsigned u = (e & 0x80000000u) ? (e ^ 0x80000000u) : ~e;
    return __uint_as_float(u);
}

__global__ __launch_bounds__(256, 3)
void fused_kernel(const float4* __restrict__ x, float4* __restrict__ out) {
    const int blk = blockIdx.x;
    const int b   = blk >> 7;            // batch (batch-major launch order)
    const int grp = blk & (GPB - 1);     // row-group within batch
    const int tid  = threadIdx.x;
    const int w4   = tid & 63;
    const int sub  = tid >> 6;           // 0..3
    const int lane = tid & 31;
    const int wid  = tid >> 5;
    const int r0   = grp * ROWS + sub * RPT;   // first output row for this thread

    const float4* __restrict__ xb = x + (size_t)b * H * W4;

    // ---- Phase 1: pool 8 output rows into registers, track local min/max ----
    float4 v[RPT];
    float4 prev;
    if (r0 == 0) {
        prev = make_float4(-CUDART_INF_F, -CUDART_INF_F, -CUDART_INF_F, -CUDART_INF_F);
    } else {
        prev = __ldcs(&xb[(size_t)(2 * r0 - 1) * W4 + w4]);
    }
    float mn =  CUDART_INF_F;
    float mx = -CUDART_INF_F;
    #pragma unroll
    for (int i = 0; i < RPT; i++) {
        const int r = r0 + i;
        float4 a = __ldcs(&xb[(size_t)(2 * r)     * W4 + w4]);
        float4 c = __ldcs(&xb[(size_t)(2 * r + 1) * W4 + w4]);
        float4 p;
        p.x = fmaxf(fmaxf(a.x, c.x), prev.x);
        p.y = fmaxf(fmaxf(a.y, c.y), prev.y);
        p.z = fmaxf(fmaxf(a.z, c.z), prev.z);
        p.w = fmaxf(fmaxf(a.w, c.w), prev.w);
        v[i] = p;
        mn = fminf(mn, fminf(fminf(p.x, p.y), fminf(p.z, p.w)));
        mx = fmaxf(mx, fmaxf(fmaxf(p.x, p.y), fmaxf(p.z, p.w)));
        prev = c;
    }

    // ---- Block reduce min/max, publish ----
    #pragma unroll
    for (int off = 16; off > 0; off >>= 1) {
        mn = fminf(mn, __shfl_xor_sync(0xFFFFFFFFu, mn, off));
        mx = fmaxf(mx, __shfl_xor_sync(0xFFFFFFFFu, mx, off));
    }
    __shared__ float s_mn[8], s_mx[8];
    if (lane == 0) { s_mn[wid] = mn; s_mx[wid] = mx; }
    __syncthreads();
    if (wid == 0) {
        mn = (lane < 8) ? s_mn[lane] :  CUDART_INF_F;
        mx = (lane < 8) ? s_mx[lane] : -CUDART_INF_F;
        #pragma unroll
        for (int off = 4; off > 0; off >>= 1) {
            mn = fminf(mn, __shfl_xor_sync(0xFFFFFFFFu, mn, off));
            mx = fmaxf(mx, __shfl_xor_sync(0xFFFFFFFFu, mx, off));
        }
        if (lane == 0) {
            atomicMin(&g_min[b], enc_f(mn));
            atomicMax(&g_max[b], enc_f(mx));
            __threadfence();                        // release
            atomicAdd(&g_pool_cnt[b], 1);
        }
    }

    // ---- Wait for whole batch to finish pooling ----
    if (tid == 0) {
        while (*(volatile int*)&g_pool_cnt[b] < GPB) __nanosleep(64);
    }
    __syncthreads();
    __threadfence();                                // acquire

    const float mnv = dec_f(*(volatile unsigned*)&g_min[b]);
    const float mxv = dec_f(*(volatile unsigned*)&g_max[b]);
    const float inv = 1.0f / (mxv - mnv);

    // ---- Phase 2: normalize from registers, stream to output ----
    float4* __restrict__ ob = out + (size_t)b * HO * W4;
    #pragma unroll
    for (int i = 0; i < RPT; i++) {
        float4 p = v[i];
        p.x = (p.x - mnv) * inv;
        p.y = (p.y - mnv) * inv;
        p.z = (p.z - mnv) * inv;
        p.w = (p.w - mnv) * inv;
        __stcs(&ob[(size_t)(r0 + i) * W4 + w4], p);
    }

    // ---- Self-reset for next replay: last block of the batch restores state ----
    __syncthreads();
    if (tid == 0) {
        int d = atomicAdd(&g_done_cnt[b], 1);
        if (d == GPB - 1) {
            *(volatile unsigned*)&g_min[b] = 0xFFFFFFFFu;
            *(volatile unsigned*)&g_max[b] = 0x00000000u;
            *(volatile int*)&g_pool_cnt[b] = 0;
            *(volatile int*)&g_done_cnt[b] = 0;
            __threadfence();
        }
    }
}

extern "C" void kernel_launch(void* const* d_in, const int* in_sizes, int n_in,
                              void* d_out, int out_size) {
    (void)in_sizes; (void)n_in; (void)out_size;
    const float4* x = (const float4*)d_in[0];
    float4* out = (float4*)d_out;
    fused_kernel<<<NBLK, 256>>>(x, out);
}

// round 4
// speedup vs baseline: 2.4085x; 1.2082x over previous
#include <cuda_runtime.h>
#include <math_constants.h>

// Fixed shapes
#define B     32
#define H     8192
#define HO    4096
#define W4    64          // 256 floats / 4
#define GPB   128         // blocks (groups) per batch
#define ROWS  32          // output rows per block
#define RPT   8           // output rows per thread (ROWS / 4 subs)
#define NBLK  (B * GPB)   // 4096

// Per-batch sync/reduction state. Static-initialized for the first launch;
// the last finishing block of each batch resets it for the next graph replay.
__device__ unsigned g_min[B] = {
    0xFFFFFFFFu,0xFFFFFFFFu,0xFFFFFFFFu,0xFFFFFFFFu,0xFFFFFFFFu,0xFFFFFFFFu,0xFFFFFFFFu,0xFFFFFFFFu,
    0xFFFFFFFFu,0xFFFFFFFFu,0xFFFFFFFFu,0xFFFFFFFFu,0xFFFFFFFFu,0xFFFFFFFFu,0xFFFFFFFFu,0xFFFFFFFFu,
    0xFFFFFFFFu,0xFFFFFFFFu,0xFFFFFFFFu,0xFFFFFFFFu,0xFFFFFFFFu,0xFFFFFFFFu,0xFFFFFFFFu,0xFFFFFFFFu,
    0xFFFFFFFFu,0xFFFFFFFFu,0xFFFFFFFFu,0xFFFFFFFFu,0xFFFFFFFFu,0xFFFFFFFFu,0xFFFFFFFFu,0xFFFFFFFFu};
__device__ unsigned g_max[B];        // zero-init == encoded -inf side
__device__ int g_pool_cnt[B];        // zero-init
__device__ int g_done_cnt[B];        // zero-init

__device__ __forceinline__ unsigned enc_f(float f) {
    unsigned u = __float_as_uint(f);
    return (u & 0x80000000u) ? ~u : (u | 0x80000000u);
}
__device__ __forceinline__ float dec_f(unsigned e) {
    unsigned u = (e & 0x80000000u) ? (e ^ 0x80000000u) : ~e;
    return __uint_as_float(u);
}

__global__ __launch_bounds__(256, 6)
void fused_kernel(const float4* __restrict__ x, float4* __restrict__ out) {
    __shared__ float4 tile[ROWS * W4];       // 32 KiB pooled staging
    __shared__ float  s_mn[8], s_mx[8];

    const int blk = blockIdx.x;
    const int b   = blk >> 7;            // batch (batch-major launch order)
    const int grp = blk & (GPB - 1);     // row-group within batch
    const int tid  = threadIdx.x;
    const int w4   = tid & 63;
    const int sub  = tid >> 6;           // 0..3
    const int lane = tid & 31;
    const int wid  = tid >> 5;
    const int r0   = grp * ROWS + sub * RPT;   // first output row for this thread
    const int lr0  = sub * RPT;                // local row in tile

    const float4* __restrict__ xb = x + (size_t)b * H * W4;

    // ---- Phase 1: pool 8 output rows -> smem tile, track local min/max ----
    float4 prev;
    if (r0 == 0) {
        prev = make_float4(-CUDART_INF_F, -CUDART_INF_F, -CUDART_INF_F, -CUDART_INF_F);
    } else {
        prev = __ldcs(&xb[(size_t)(2 * r0 - 1) * W4 + w4]);
    }
    float mn =  CUDART_INF_F;
    float mx = -CUDART_INF_F;
    #pragma unroll
    for (int i = 0; i < RPT; i++) {
        const int r = r0 + i;
        float4 a = __ldcs(&xb[(size_t)(2 * r)     * W4 + w4]);
        float4 c = __ldcs(&xb[(size_t)(2 * r + 1) * W4 + w4]);
        float4 p;
        p.x = fmaxf(fmaxf(a.x, c.x), prev.x);
        p.y = fmaxf(fmaxf(a.y, c.y), prev.y);
        p.z = fmaxf(fmaxf(a.z, c.z), prev.z);
        p.w = fmaxf(fmaxf(a.w, c.w), prev.w);
        tile[(lr0 + i) * W4 + w4] = p;
        mn = fminf(mn, fminf(fminf(p.x, p.y), fminf(p.z, p.w)));
        mx = fmaxf(mx, fmaxf(fmaxf(p.x, p.y), fmaxf(p.z, p.w)));
        prev = c;
    }

    // ---- Block reduce min/max, publish ----
    #pragma unroll
    for (int off = 16; off > 0; off >>= 1) {
        mn = fminf(mn, __shfl_xor_sync(0xFFFFFFFFu, mn, off));
        mx = fmaxf(mx, __shfl_xor_sync(0xFFFFFFFFu, mx, off));
    }
    if (lane == 0) { s_mn[wid] = mn; s_mx[wid] = mx; }
    __syncthreads();
    if (wid == 0) {
        mn = (lane < 8) ? s_mn[lane] :  CUDART_INF_F;
        mx = (lane < 8) ? s_mx[lane] : -CUDART_INF_F;
        #pragma unroll
        for (int off = 4; off > 0; off >>= 1) {
            mn = fminf(mn, __shfl_xor_sync(0xFFFFFFFFu, mn, off));
            mx = fmaxf(mx, __shfl_xor_sync(0xFFFFFFFFu, mx, off));
        }
        if (lane == 0) {
            atomicMin(&g_min[b], enc_f(mn));
            atomicMax(&g_max[b], enc_f(mx));
            __threadfence();                        // release
            atomicAdd(&g_pool_cnt[b], 1);
        }
    }

    // ---- Wait for whole batch to finish pooling ----
    if (tid == 0) {
        while (*(volatile int*)&g_pool_cnt[b] < GPB) __nanosleep(64);
    }
    __syncthreads();

    const float mnv = dec_f(*(volatile unsigned*)&g_min[b]);
    const float mxv = dec_f(*(volatile unsigned*)&g_max[b]);
    const float inv = 1.0f / (mxv - mnv);

    // ---- Phase 2: normalize from smem, stream to output ----
    float4* __restrict__ ob = out + (size_t)b * HO * W4;
    #pragma unroll
    for (int i = 0; i < RPT; i++) {
        float4 p = tile[(lr0 + i) * W4 + w4];   // own writes: no extra sync needed
        p.x = (p.x - mnv) * inv;
        p.y = (p.y - mnv) * inv;
        p.z = (p.z - mnv) * inv;
        p.w = (p.w - mnv) * inv;
        __stcs(&ob[(size_t)(r0 + i) * W4 + w4], p);
    }

    // ---- Self-reset for next replay: last block of the batch restores state ----
    __syncthreads();
    if (tid == 0) {
        int d = atomicAdd(&g_done_cnt[b], 1);
        if (d == GPB - 1) {
            *(volatile unsigned*)&g_min[b] = 0xFFFFFFFFu;
            *(volatile unsigned*)&g_max[b] = 0x00000000u;
            *(volatile int*)&g_pool_cnt[b] = 0;
            *(volatile int*)&g_done_cnt[b] = 0;
            __threadfence();
        }
    }
}

extern "C" void kernel_launch(void* const* d_in, const int* in_sizes, int n_in,
                              void* d_out, int out_size) {
    (void)in_sizes; (void)n_in; (void)out_size;
    const float4* x = (const float4*)d_in[0];
    float4* out = (float4*)d_out;
    fused_kernel<<<NBLK, 256>>>(x, out);
}